// round 3
// baseline (speedup 1.0000x reference)
#include <cuda_runtime.h>

#define Bn 128
#define Tn 1024
#define Kn 16
#define STAGES 16
#define CH 32
#define NCHUNK (Tn/CH)

// 8MB staging for normalized y_seq (device global: allocation-free scratch)
__device__ float YBUF[Bn * Tn * Kn];

static __device__ __forceinline__ float ex2f(float x){ float r; asm("ex2.approx.f32 %0, %1;" : "=f"(r) : "f"(x)); return r; }
static __device__ __forceinline__ float lg2f(float x){ float r; asm("lg2.approx.f32 %0, %1;" : "=f"(r) : "f"(x)); return r; }
static __device__ __forceinline__ float rcpf(float x){ float r; asm("rcp.approx.f32 %0, %1;" : "=f"(r) : "f"(x)); return r; }
static __device__ __forceinline__ void cp16(unsigned s, const float* g){
  asm volatile("cp.async.ca.shared.global [%0], [%1], 16;" :: "r"(s), "l"(g) : "memory");
}

struct ScanSmem {
  float L[STAGES][Kn*Kn];   // logits ring: 16 KB (16-step prefetch depth)
  float G[STAGES][Kn];      // gumbel ring
  float EN[2][CH][Kn];      // unnormalized e_t, chunk double-buffered
  float LL[2][CH][Kn];      // normalized mixed logits l_t
  float YST[CH][Kn];        // y staging for coalesced dump (stats warp private)
};

// ============================ kernel 1: sequential scan ============================
__global__ void __launch_bounds__(64,1) scan_kernel(
 const float* __restrict__ logits, const float* __restrict__ gum,
 const float* __restrict__ trP, float* __restrict__ oLq, float* __restrict__ oLp)
{
  __shared__ ScanSmem sm;
  const int b = blockIdx.x;
  const int tid = threadIdx.x;
  const int wid = tid >> 5, lane = tid & 31;
  const float LOG2E = 1.4426950408889634f;
  const float LN2   = 0.69314718055994531f;
  const float C2L   = 2.0f * LOG2E;          // (1/tau)*log2(e), tau=0.5

  if (wid == 0) {
    // ---------------- producer warp: minimal recurrence only ----------------
    const int j = lane & 15;                 // lanes 16..31 mirror 0..15
    const float* Lb = logits + (size_t)b * Tn * 256;
    const float* Gb = gum    + (size_t)b * Tn * 16;
    unsigned sL0 = (unsigned)__cvta_generic_to_shared(&sm.L[0][0]);
    unsigned sG0 = (unsigned)__cvta_generic_to_shared(&sm.G[0][0]);
    // prologue: 16 stages as 8 groups of 2
    #pragma unroll
    for (int s = 0; s < STAGES; ++s) {
      cp16(sL0 + s*1024 + lane*32,      Lb + s*256 + lane*8);
      cp16(sL0 + s*1024 + lane*32 + 16, Lb + s*256 + lane*8 + 4);
      if (lane < 4) cp16(sG0 + s*64 + lane*16, Gb + s*16 + lane*4);
      if (s & 1) asm volatile("cp.async.commit_group;" ::: "memory");
    }

    float e = 1.0f;  // unnormalized weights of y_prev; e=1 <=> uniform
    for (int c = 0; c <= NCHUNK; ++c) {
      if (c < NCHUNK) {
        const int buf = c & 1;
        for (int i = 0; i < CH; ++i) {
          const int t = c*CH + i;
          const int st = t & (STAGES-1);
          // paired commits: wait_group 7 <=> <=14 stages pending -> stage t ready,
          // with a 16-step issue->consume window (~1600 cyc) hiding DRAM latency.
          asm volatile("cp.async.wait_group 7;" ::: "memory");
          __syncwarp();
          float Lc[Kn];
          #pragma unroll
          for (int k = 0; k < Kn; ++k) Lc[k] = sm.L[st][k*Kn + j];
          float gz = sm.G[st][j] * C2L;
          // refill same slot for t+16 (reads above already issued; DMA lands much later)
          { int tn = t + STAGES;
            if (tn < Tn) {
              int sn = tn & (STAGES-1);
              cp16(sL0 + sn*1024 + lane*32,      Lb + tn*256 + lane*8);
              cp16(sL0 + sn*1024 + lane*32 + 16, Lb + tn*256 + lane*8 + 4);
              if (lane < 4) cp16(sG0 + sn*64 + lane*16, Gb + tn*16 + lane*4);
            }
            if (t & 1) asm volatile("cp.async.commit_group;" ::: "memory");
          }
          // critical path: parallel shfl broadcasts -> product tree + sum tree
          float ek[Kn];
          #pragma unroll
          for (int k = 0; k < Kn; ++k) ek[k] = __shfl_sync(0xffffffffu, e, k);
          float p[Kn];
          #pragma unroll
          for (int k = 0; k < Kn; ++k) p[k] = ek[k] * Lc[k];
          float u = ((((p[0]+p[1])+(p[2]+p[3]))+((p[4]+p[5])+(p[6]+p[7])))
                  + (((p[8]+p[9])+(p[10]+p[11]))+((p[12]+p[13])+(p[14]+p[15]))));
          float S = ((((ek[0]+ek[1])+(ek[2]+ek[3]))+((ek[4]+ek[5])+(ek[6]+ek[7])))
                  + (((ek[8]+ek[9])+(ek[10]+ek[11]))+((ek[12]+ek[13])+(ek[14]+ek[15]))));
          float r  = rcpf(S);
          float en = ex2f(fmaf(u, r * C2L, gz));   // exp((l+g)/tau)
          float l  = u * r;                         // off critical path
          if (lane < Kn) { sm.EN[buf][i][j] = en; sm.LL[buf][i][j] = l; }
          e = en;
        }
      }
      __syncthreads();
    }
  } else {
    // ---------------- stats warp (own SMSP): normalize + log_q/log_p ----------------
    const int j = lane & 15;
    float logPc[Kn];
    #pragma unroll
    for (int k = 0; k < Kn; ++k) logPc[k] = lg2f(trP[k*Kn + j]) * LN2;
    float yprev = 1.0f / 16.0f;
    for (int c = 0; c <= NCHUNK; ++c) {
      if (c >= 1) {
        const int buf = (c-1) & 1;
        const int t0 = (c-1) * CH;
        for (int i = 0; i < CH; ++i) {
          const int t = t0 + i;
          float en = sm.EN[buf][i][j];
          float l  = sm.LL[buf][i][j];
          float Se = en;
          #pragma unroll
          for (int d = 8; d; d >>= 1) Se += __shfl_xor_sync(0xffffffffu, Se, d);
          float y = en * rcpf(Se);
          if (lane < Kn) sm.YST[i][j] = y;
          float wr = 0.f;  // (y_prev^T logP)_j
          #pragma unroll
          for (int k = 0; k < Kn; ++k) {
            float yk = __shfl_sync(0xffffffffu, yprev, k);
            wr = fmaf(yk, logPc[k], wr);
          }
          float sel = ex2f(l * LOG2E);
          float syl = y * l;
          float slp = y * wr;
          #pragma unroll
          for (int d = 8; d; d >>= 1) {
            sel += __shfl_xor_sync(0xffffffffu, sel, d);
            syl += __shfl_xor_sync(0xffffffffu, syl, d);
            slp += __shfl_xor_sync(0xffffffffu, slp, d);
          }
          float lq = syl - lg2f(sel) * LN2;
          float lp = (t == 0) ? -2.7725887222397811f : slp;  // t=0: -log K
          if (lane == 0) {
            oLq[(size_t)b*Tn + t] = lq;
            oLp[(size_t)b*Tn + t] = lp;
          }
          yprev = y;
        }
        // coalesced dump: 32 steps x 64B = 2KB contiguous
        const float4* ys4 = (const float4*)&sm.YST[0][0];
        float4* yb4 = (float4*)&YBUF[((size_t)b*Tn + t0) * Kn];
        #pragma unroll
        for (int r2 = 0; r2 < 4; ++r2) yb4[r2*32 + lane] = ys4[r2*32 + lane];
      }
      __syncthreads();
    }
  }
}

// ============================ kernel 2: mixing epilogue ============================
// A_seq|B_seq = y(131072x16) @ [A|B](16x384), massively parallel, store-bound.
__global__ void __launch_bounds__(192) mix_kernel(
 const float* __restrict__ Am, const float* __restrict__ Bmm,
 const float* __restrict__ Cm,
 float* __restrict__ oA, float* __restrict__ oB, float* __restrict__ oC)
{
  __shared__ float yc[CH][Kn];
  const int bid = blockIdx.x;          // 1024 blocks
  const int b  = bid >> 3;
  const int tq = bid & 7;              // 8 chunks of 128 timesteps
  const int tid = threadIdx.x;
  const int g  = tid / 96;             // 2 groups of 96 threads; group handles alternate t
  const int gq = tid % 96;
  const int cols = gq * 4;             // 4 output cols per thread
  const bool isA = cols < 256;
  float c0[Kn], c1[Kn], c2[Kn], c3[Kn];
  #pragma unroll
  for (int k = 0; k < Kn; ++k) {
    if (isA) {
      c0[k] = Am[k*256 + cols];     c1[k] = Am[k*256 + cols + 1];
      c2[k] = Am[k*256 + cols + 2]; c3[k] = Am[k*256 + cols + 3];
    } else {
      int eb = cols - 256;
      c0[k] = Bmm[k*128 + eb];      c1[k] = Bmm[k*128 + eb + 1];
      c2[k] = Bmm[k*128 + eb + 2];  c3[k] = Bmm[k*128 + eb + 3];
    }
  }
  const size_t btbase = (size_t)b * Tn + tq * 128;
  for (int ch = 0; ch < 4; ++ch) {
    const int t0 = ch * 32;
    if (tid < 128)
      ((float4*)yc)[tid] = ((const float4*)&YBUF[(btbase + t0) * Kn])[tid];
    __syncthreads();
    for (int ii = 0; ii < 16; ++ii) {
      const int tt = ii*2 + g;
      float a0=0.f,a1=0.f,a2=0.f,a3=0.f;
      #pragma unroll
      for (int k = 0; k < Kn; ++k) {
        float yk = yc[tt][k];                      // LDS broadcast
        a0 = fmaf(yk, c0[k], a0); a1 = fmaf(yk, c1[k], a1);
        a2 = fmaf(yk, c2[k], a2); a3 = fmaf(yk, c3[k], a3);
      }
      const size_t t = btbase + t0 + tt;
      float4 v = make_float4(a0,a1,a2,a3);
      if (isA) *(float4*)(oA + t*256 + cols) = v;
      else     *(float4*)(oB + t*128 + (cols - 256)) = v;
    }
    __syncthreads();
  }
  if (tq == 0 && tid < 128)
    ((float4*)(oC + (size_t)b*512))[tid] = ((const float4*)Cm)[tid];
}

extern "C" void kernel_launch(void* const* d_in, const int* in_sizes, int n_in,
                              void* d_out, int out_size) {
  const float* logits = (const float*)d_in[0];
  const float* gum    = (const float*)d_in[1];
  const float* Am     = (const float*)d_in[2];
  const float* Bmm    = (const float*)d_in[3];
  const float* Cm     = (const float*)d_in[4];
  const float* trP    = (const float*)d_in[5];
  float* out = (float*)d_out;
  // output layout: A_seq | B_seq | C_seq | log_qseq | log_pseq
  float* oA  = out;                               // 128*1024*256
  float* oB  = out + 33554432ull;                 // 128*1024*128
  float* oC  = out + 50331648ull;                 // 128*512
  float* oLq = out + 50397184ull;                 // 128*1024
  float* oLp = out + 50528256ull;                 // 128*1024
  scan_kernel<<<Bn, 64>>>(logits, gum, trP, oLq, oLp);
  mix_kernel<<<1024, 192>>>(Am, Bmm, Cm, oA, oB, oC);
}

// round 4
// speedup vs baseline: 1.2284x; 1.2284x over previous
#include <cuda_runtime.h>

#define Bn 128
#define Tn 1024
#define Kn 16
#define STAGES 16

// Scratch (device globals: allocation-free):
__device__ float2 ELBUF[Bn * Tn * Kn];  // 16MB: (en_unnormalized, l_normalized) per (b,t,j)
__device__ float  YBUF [Bn * Tn * Kn];  // 8MB: normalized y

static __device__ __forceinline__ float ex2f(float x){ float r; asm("ex2.approx.f32 %0, %1;" : "=f"(r) : "f"(x)); return r; }
static __device__ __forceinline__ float lg2f(float x){ float r; asm("lg2.approx.f32 %0, %1;" : "=f"(r) : "f"(x)); return r; }
static __device__ __forceinline__ float rcpf(float x){ float r; asm("rcp.approx.f32 %0, %1;" : "=f"(r) : "f"(x)); return r; }
static __device__ __forceinline__ void cp16(unsigned s, const float* g){
  asm volatile("cp.async.ca.shared.global [%0], [%1], 16;" :: "r"(s), "l"(g) : "memory");
}
#define FMA2(d,a,b,c) asm("fma.rn.f32x2 %0, %1, %2, %3;" : "=l"(d) : "l"(a), "l"(b), "l"(c))

// ===================== kernel 1: sequential scan — ZERO shuffles =====================
__global__ void __launch_bounds__(32,1) scan_kernel(
 const float* __restrict__ logits, const float* __restrict__ gum)
{
  __shared__ __align__(16) float L[STAGES][Kn*Kn];  // 16KB logits ring
  __shared__ __align__(16) float G[STAGES][Kn];
  __shared__ __align__(16) float E[Kn];             // e-vector exchange buffer
  const int b = blockIdx.x;
  const int lane = threadIdx.x;
  const int j = lane & 15;                           // lanes 16..31 mirror 0..15
  const float C2L = 2.8853900817779268f;             // (1/tau)*log2(e), tau=0.5

  const float* Lb = logits + (size_t)b * Tn * 256;
  const float* Gb = gum    + (size_t)b * Tn * 16;
  float2* ELb = ELBUF + (size_t)b * Tn * Kn;
  unsigned sL0 = (unsigned)__cvta_generic_to_shared(&L[0][0]);
  unsigned sG0 = (unsigned)__cvta_generic_to_shared(&G[0][0]);

  #pragma unroll
  for (int s = 0; s < STAGES; ++s) {                 // prologue: 8 groups of 2 stages
    cp16(sL0 + s*1024 + lane*32,      Lb + s*256 + lane*8);
    cp16(sL0 + s*1024 + lane*32 + 16, Lb + s*256 + lane*8 + 4);
    if (lane < 4) cp16(sG0 + s*64 + lane*16, Gb + s*16 + lane*4);
    if (s & 1) asm volatile("cp.async.commit_group;" ::: "memory");
  }

  float ek[Kn];
  #pragma unroll
  for (int k = 0; k < Kn; ++k) ek[k] = 1.0f;         // e=1 <=> uniform y0

  for (int t = 0; t < Tn; ++t) {
    const int st = t & (STAGES-1);
    // paired commits: wait 7 <=> stages t..t+1 resident; 15-step flight window
    asm volatile("cp.async.wait_group 7;" ::: "memory");
    __syncwarp();
    float Lc[Kn];
    #pragma unroll
    for (int k = 0; k < Kn; ++k) Lc[k] = L[st][k*Kn + j];   // column j (bcast halves)
    float gz = G[st][j] * C2L;
    // refill slot for t+16 (reads above already issued; DMA lands much later)
    { int tn = t + STAGES;
      if (tn < Tn) {
        cp16(sL0 + st*1024 + lane*32,      Lb + tn*256 + lane*8);
        cp16(sL0 + st*1024 + lane*32 + 16, Lb + tn*256 + lane*8 + 4);
        if (lane < 4) cp16(sG0 + st*64 + lane*16, Gb + tn*16 + lane*4);
      }
      if (t & 1) asm volatile("cp.async.commit_group;" ::: "memory");
    }
    // dual trees: u_j = sum_k e_k L_kj ; S = sum_k e_k   (no shuffles)
    float p[Kn];
    #pragma unroll
    for (int k = 0; k < Kn; ++k) p[k] = ek[k] * Lc[k];
    float u = ((((p[0]+p[1])+(p[2]+p[3]))+((p[4]+p[5])+(p[6]+p[7])))
            + (((p[8]+p[9])+(p[10]+p[11]))+((p[12]+p[13])+(p[14]+p[15]))));
    float S = ((((ek[0]+ek[1])+(ek[2]+ek[3]))+((ek[4]+ek[5])+(ek[6]+ek[7])))
            + (((ek[8]+ek[9])+(ek[10]+ek[11]))+((ek[12]+ek[13])+(ek[14]+ek[15]))));
    float r  = rcpf(S);
    float en = ex2f(fmaf(u, r * C2L, gz));           // exp((l+g)/tau)
    float l  = u * r;                                // off critical path
    if (lane < Kn) {
      E[j] = en;
      ELb[t*Kn + j] = make_float2(en, l);            // 128B coalesced dump
    }
    __syncwarp();
    // reload full e-vector: 4x LDS.128 broadcast
    float4 e0 = *(const float4*)&E[0];
    float4 e1 = *(const float4*)&E[4];
    float4 e2 = *(const float4*)&E[8];
    float4 e3 = *(const float4*)&E[12];
    ek[0]=e0.x; ek[1]=e0.y; ek[2]=e0.z; ek[3]=e0.w;
    ek[4]=e1.x; ek[5]=e1.y; ek[6]=e1.z; ek[7]=e1.w;
    ek[8]=e2.x; ek[9]=e2.y; ek[10]=e2.z; ek[11]=e2.w;
    ek[12]=e3.x; ek[13]=e3.y; ek[14]=e3.z; ek[15]=e3.w;
  }
}

// ===================== kernel 2: normalize + stats (fully parallel) =====================
__global__ void __launch_bounds__(256) norm_stats(
 const float* __restrict__ trP, float* __restrict__ oLq, float* __restrict__ oLp)
{
  __shared__ float4 WP[Kn][4];                       // log(transP) rows as float4
  const float LOG2E = 1.4426950408889634f;
  const float LN2   = 0.69314718055994531f;
  const int tid = threadIdx.x;
  if (tid < 64) {
    int i = tid >> 2, q = tid & 3;
    const float* rr = trP + i*16 + q*4;
    WP[i][q] = make_float4(lg2f(rr[0])*LN2, lg2f(rr[1])*LN2,
                           lg2f(rr[2])*LN2, lg2f(rr[3])*LN2);
  }
  __syncthreads();
  const int gid = blockIdx.x * 256 + tid;            // (b,t) flattened: 131072 threads
  const float4* p = (const float4*)(ELBUF + (size_t)gid * Kn);
  float en[Kn], l[Kn];
  #pragma unroll
  for (int q = 0; q < 8; ++q) {
    float4 v = p[q];
    en[2*q] = v.x; l[2*q] = v.y; en[2*q+1] = v.z; l[2*q+1] = v.w;
  }
  float Se = 0.f;
  #pragma unroll
  for (int k = 0; k < Kn; ++k) Se += en[k];
  float r = rcpf(Se);
  float y[Kn];
  #pragma unroll
  for (int k = 0; k < Kn; ++k) y[k] = en[k] * r;
  float4* yo = (float4*)(YBUF + (size_t)gid * Kn);
  yo[0] = make_float4(y[0],y[1],y[2],y[3]);
  yo[1] = make_float4(y[4],y[5],y[6],y[7]);
  yo[2] = make_float4(y[8],y[9],y[10],y[11]);
  yo[3] = make_float4(y[12],y[13],y[14],y[15]);
  float sel = 0.f, syl = 0.f;
  #pragma unroll
  for (int k = 0; k < Kn; ++k) { sel += ex2f(l[k]*LOG2E); syl = fmaf(y[k], l[k], syl); }
  float lq = syl - lg2f(sel)*LN2;                    // sum y*(l - lse(l))
  const int t = gid & (Tn-1);
  float lp = -2.7725887222397811f;                   // t=0: -log K
  if (t) {
    const float4* pp = (const float4*)(ELBUF + (size_t)(gid-1) * Kn);
    float enp[Kn];
    #pragma unroll
    for (int q = 0; q < 8; ++q) { float4 v = pp[q]; enp[2*q] = v.x; enp[2*q+1] = v.z; }
    float Sp = 0.f;
    #pragma unroll
    for (int k = 0; k < Kn; ++k) Sp += enp[k];
    float rp = rcpf(Sp);
    float acc = 0.f;
    #pragma unroll
    for (int i = 0; i < Kn; ++i) {                   // acc = sum_i enp_i * (logP y)_i
      float4 w0 = WP[i][0], w1 = WP[i][1], w2 = WP[i][2], w3 = WP[i][3];
      float z = w0.x*y[0];
      z = fmaf(w0.y,y[1], z); z = fmaf(w0.z,y[2], z); z = fmaf(w0.w,y[3], z);
      z = fmaf(w1.x,y[4], z); z = fmaf(w1.y,y[5], z); z = fmaf(w1.z,y[6], z); z = fmaf(w1.w,y[7], z);
      z = fmaf(w2.x,y[8], z); z = fmaf(w2.y,y[9], z); z = fmaf(w2.z,y[10],z); z = fmaf(w2.w,y[11],z);
      z = fmaf(w3.x,y[12],z); z = fmaf(w3.y,y[13],z); z = fmaf(w3.z,y[14],z); z = fmaf(w3.w,y[15],z);
      acc = fmaf(enp[i], z, acc);
    }
    lp = acc * rp;
  }
  oLq[gid] = lq;
  oLp[gid] = lp;
}

// ===================== kernel 3: mixing epilogue with packed f32x2 FMA =====================
__global__ void __launch_bounds__(192) mix_kernel(
 const float* __restrict__ Am, const float* __restrict__ Bmm,
 const float* __restrict__ Cm,
 float* __restrict__ oA, float* __restrict__ oB, float* __restrict__ oC)
{
  __shared__ __align__(16) float2 ycd[32][Kn];       // y duplicated as (y,y): 4KB
  const int bid = blockIdx.x;                        // 4096 blocks
  const int b  = bid >> 5;
  const int tc = bid & 31;                           // 32-timestep chunk
  const int tid = threadIdx.x;
  const int g  = tid / 96;                           // 2 groups alternate timesteps
  const int gq = tid % 96;
  const int cols = gq * 4;
  const bool isA = cols < 256;
  unsigned long long cc0[Kn], cc1[Kn];               // packed column pairs
  #pragma unroll
  for (int k = 0; k < Kn; ++k) {
    float a,bb,cx,d;
    if (isA) { const float* s = Am + k*256 + cols;       a=s[0]; bb=s[1]; cx=s[2]; d=s[3]; }
    else     { const float* s = Bmm + k*128 + (cols-256); a=s[0]; bb=s[1]; cx=s[2]; d=s[3]; }
    asm("mov.b64 %0, {%1,%2};" : "=l"(cc0[k]) : "f"(a),  "f"(bb));
    asm("mov.b64 %0, {%1,%2};" : "=l"(cc1[k]) : "f"(cx), "f"(d));
  }
  const size_t btbase = (size_t)b * Tn + tc * 32;
  if (tid < 128) {                                   // stage duplicated y
    float4 v = ((const float4*)(YBUF + btbase * Kn))[tid];
    float2* d = &ycd[tid >> 2][(tid & 3) * 4];
    d[0] = make_float2(v.x,v.x); d[1] = make_float2(v.y,v.y);
    d[2] = make_float2(v.z,v.z); d[3] = make_float2(v.w,v.w);
  }
  __syncthreads();
  for (int ii = 0; ii < 16; ++ii) {
    const int tt = ii*2 + g;
    const ulonglong2* yr = (const ulonglong2*)&ycd[tt][0];
    unsigned long long yy[Kn];
    #pragma unroll
    for (int q = 0; q < 8; ++q) { ulonglong2 w = yr[q]; yy[2*q] = w.x; yy[2*q+1] = w.y; }
    unsigned long long a01 = 0ull, a23 = 0ull;       // (0.f,0.f)
    #pragma unroll
    for (int k = 0; k < Kn; ++k) { FMA2(a01, yy[k], cc0[k], a01); FMA2(a23, yy[k], cc1[k], a23); }
    unsigned r0,r1,r2,r3;
    asm("mov.b64 {%0,%1}, %2;" : "=r"(r0), "=r"(r1) : "l"(a01));
    asm("mov.b64 {%0,%1}, %2;" : "=r"(r2), "=r"(r3) : "l"(a23));
    float4 v = make_float4(__uint_as_float(r0), __uint_as_float(r1),
                           __uint_as_float(r2), __uint_as_float(r3));
    const size_t t = btbase + tt;
    if (isA) *(float4*)(oA + t*256 + cols) = v;
    else     *(float4*)(oB + t*128 + (cols - 256)) = v;
  }
  if (tc == 0 && tid < 128)
    ((float4*)(oC + (size_t)b*512))[tid] = ((const float4*)Cm)[tid];
}

extern "C" void kernel_launch(void* const* d_in, const int* in_sizes, int n_in,
                              void* d_out, int out_size) {
  const float* logits = (const float*)d_in[0];
  const float* gum    = (const float*)d_in[1];
  const float* Am     = (const float*)d_in[2];
  const float* Bmm    = (const float*)d_in[3];
  const float* Cm     = (const float*)d_in[4];
  const float* trP    = (const float*)d_in[5];
  float* out = (float*)d_out;
  // output layout: A_seq | B_seq | C_seq | log_qseq | log_pseq
  float* oA  = out;                               // 128*1024*256
  float* oB  = out + 33554432ull;                 // 128*1024*128
  float* oC  = out + 50331648ull;                 // 128*512
  float* oLq = out + 50397184ull;                 // 128*1024
  float* oLp = out + 50528256ull;                 // 128*1024
  scan_kernel<<<Bn, 32>>>(logits, gum);
  norm_stats<<<512, 256>>>(trP, oLq, oLp);
  mix_kernel<<<4096, 192>>>(Am, Bmm, Cm, oA, oB, oC);
}